// round 13
// baseline (speedup 1.0000x reference)
#include <cuda_runtime.h>
#include <cstdint>
#include <math.h>

#define BATCH 64
#define CIN   128
#define OCH   128
#define H     80
#define W     80
#define HW    6400
#define MTILE 128            // pixels per CTA
#define NCHUNK 36            // 9 taps * 4 ic-chunks of 32
#define NTHREADS 512

// Scratch (allocation-free rule: __device__ globals)
__device__ float g_avg[BATCH * CIN * 25];                 // [b][c][5][5]
__device__ float g_dynw[(size_t)BATCH * 9 * OCH * CIN];   // [b][tap][oc][ic], tf32-rounded
__device__ float g_xt[(size_t)BATCH * HW * CIN];          // NHWC tf32-rounded copy of x

__device__ __forceinline__ uint32_t tf32r(float v) {
    uint32_t u;
    asm("cvt.rna.tf32.f32 %0, %1;" : "=r"(u) : "f"(v));
    return u;
}

__device__ __forceinline__ void mma_tf32(float* d, const uint32_t* a, const uint32_t* bq) {
    asm volatile(
        "mma.sync.aligned.m16n8k8.row.col.f32.tf32.tf32.f32 "
        "{%0,%1,%2,%3}, {%4,%5,%6,%7}, {%8,%9}, {%0,%1,%2,%3};"
        : "+f"(d[0]), "+f"(d[1]), "+f"(d[2]), "+f"(d[3])
        : "r"(a[0]), "r"(a[1]), "r"(a[2]), "r"(a[3]), "r"(bq[0]), "r"(bq[1]));
}

// fragment-index swizzles (bijective; applied identically on store & load)
__device__ __forceinline__ int swzA(int F) {
    return F ^ ((F >> 2) & 7) ^ (((F >> 7) & 1) << 1);
}
__device__ __forceinline__ int swzB(int G) {
    return G ^ ((G >> 2) & 7) ^ (((G >> 7) & 1) << 3);
}

// ---------------------------------------------------------------------------
// Kernel T: NCHW -> NHWC transpose with tf32 pre-rounding
// ---------------------------------------------------------------------------
__global__ void __launch_bounds__(256)
transform_kernel(const float* __restrict__ x) {
    __shared__ float t[32][257];
    const int tid = threadIdx.x;
    const int b   = blockIdx.y;
    const int px0 = blockIdx.x * 256;
    const float* xb  = x    + (size_t)b * CIN * HW;
    float*       xtb = g_xt + (size_t)b * HW * CIN;

    for (int pass = 0; pass < 4; pass++) {
        const int ic0 = pass * 32;
        if (pass) __syncthreads();
        #pragma unroll 4
        for (int r = 0; r < 32; r++)
            t[r][tid] = xb[(size_t)(ic0 + r) * HW + px0 + tid];
        __syncthreads();
        float* dst = xtb + (size_t)(px0 + tid) * CIN + ic0;
        #pragma unroll
        for (int q = 0; q < 8; q++) {
            float4 v;
            v.x = __uint_as_float(tf32r(t[4 * q + 0][tid]));
            v.y = __uint_as_float(tf32r(t[4 * q + 1][tid]));
            v.z = __uint_as_float(tf32r(t[4 * q + 2][tid]));
            v.w = __uint_as_float(tf32r(t[4 * q + 3][tid]));
            ((float4*)dst)[q] = v;
        }
    }
}

// ---------------------------------------------------------------------------
// Kernel A: adaptive average pool 80x80 -> 5x5 (16x16 equal tiles)
// ---------------------------------------------------------------------------
__global__ void avgpool_kernel(const float* __restrict__ x) {
    int idx = blockIdx.x * blockDim.x + threadIdx.x;
    if (idx >= BATCH * CIN * 25) return;
    int cell = idx % 25;
    int bc   = idx / 25;
    int oy = cell / 5, ox = cell % 5;
    const float* p = x + ((size_t)bc * H + oy * 16) * W + ox * 16;
    float s = 0.f;
    #pragma unroll
    for (int r = 0; r < 16; r++) {
        const float4* q = (const float4*)(p + r * W);
        #pragma unroll
        for (int j = 0; j < 4; j++) {
            float4 v = q[j];
            s += v.x + v.y + v.z + v.w;
        }
    }
    g_avg[idx] = s * (1.f / 256.f);
}

// ---------------------------------------------------------------------------
// Kernel B: attention conv (3x3 VALID on 5x5) + sigmoid + weight modulation
// Writes tf32-pre-rounded dynamic weights in layout [b][tap][oc][ic]
// ---------------------------------------------------------------------------
__global__ void att_kernel(const float* __restrict__ weight,
                           const float* __restrict__ w_att,
                           const float* __restrict__ b_att) {
    int idx = blockIdx.x * blockDim.x + threadIdx.x;   // (b*OCH + oc)*CIN + ic
    if (idx >= BATCH * OCH * CIN) return;
    int ic  = idx % CIN;
    int boc = idx / CIN;            // b*OCH + oc
    int oc  = boc % OCH;
    int b   = boc / OCH;
    int o   = oc * CIN + ic;        // attention output channel

    float a[25];
    #pragma unroll
    for (int i = 0; i < 25; i++) a[i] = g_avg[boc * 25 + i];
    float wa[9];
    #pragma unroll
    for (int i = 0; i < 9; i++) wa[i] = w_att[o * 9 + i];
    float bias = b_att[o];

    #pragma unroll
    for (int kh = 0; kh < 3; kh++) {
        #pragma unroll
        for (int kw = 0; kw < 3; kw++) {
            float s = bias;
            #pragma unroll
            for (int i = 0; i < 3; i++)
                #pragma unroll
                for (int j = 0; j < 3; j++)
                    s += a[(kh + i) * 5 + (kw + j)] * wa[i * 3 + j];
            float sig = 1.f / (1.f + expf(-s));
            int tap = kh * 3 + kw;
            float v = weight[(oc * CIN + ic) * 9 + tap] * sig;
            g_dynw[(((size_t)b * 9 + tap) * OCH + oc) * CIN + ic] = __uint_as_float(tf32r(v));
        }
    }
}

// ---------------------------------------------------------------------------
// Kernel C: tf32 mma.sync implicit-GEMM conv — 512 threads / 16 warps
// CTA: 128 pixels (M) x 128 oc (N); K = 9 taps x 128 ic in chunks of 32.
// Each thread stages ONE kstep (ih = tid>>7): 8 A floats + 8 B floats
// (2+2 LDG.128 from NHWC tf32 copy / pre-rounded weights), 4+4 STS.64 into
// fragment-order XOR-swizzled SMEM. Double-buffered, 1 __syncthreads/chunk.
// Warp grid 4(M) x 4(N), warp tile 32x32, acc 2x4x4 = 32 regs/thread.
// ---------------------------------------------------------------------------
__global__ void __launch_bounds__(NTHREADS)
conv_kernel(const float* __restrict__ xt, float* __restrict__ out) {
    extern __shared__ float smem[];   // [A0 4096][A1 4096][B0 4096][B1 4096] floats

    const int tid  = threadIdx.x;
    const int lane = tid & 31, wid = tid >> 5;
    const int b    = blockIdx.y;
    const int n0   = blockIdx.x * MTILE;

    // writer identities: pixel/oc = tid&127, kstep = tid>>7
    const int px   = tid & 127;
    const int ih   = tid >> 7;           // kstep 0..3 (8 ic each)
    const int yA   = (n0 + px) / W, xxA = (n0 + px) % W;
    const int mtw  = px >> 4;
    const int rA   = px & 15, gA = rA & 7, rhalf = rA >> 3;
    const int ocB  = tid & 127;
    const int ntw  = ocB >> 3, gB = ocB & 7;

    const float* xb    = xt + (size_t)b * HW * CIN;
    const float* wbase = g_dynw + (size_t)b * 9 * OCH * CIN;

    // mma identities: 4x4 warp grid, warp tile 32(M) x 32(N)
    const int warpM = wid & 3, warpN = wid >> 2;
    const int mtb = warpM * 2, ntb = warpN * 4;

    float acc[2][4][4];
    #pragma unroll
    for (int mf = 0; mf < 2; mf++)
        #pragma unroll
        for (int nf = 0; nf < 4; nf++)
            #pragma unroll
            for (int q = 0; q < 4; q++) acc[mf][nf][q] = 0.f;

    float areg[8];
    float breg[8];

    // ---- chunk loader (global -> regs); one kstep (8 ic) per thread ----
    #define LOAD_CHUNK(J) do {                                                  \
        int _tap = (J) >> 2, _ic0 = ((J) & 3) * 32;                             \
        int _dy = _tap / 3 - 1, _dx = _tap % 3 - 1;                             \
        int _sy = yA + _dy, _sx = xxA + _dx;                                    \
        bool _ok = (_sy >= 0) & (_sy < H) & (_sx >= 0) & (_sx < W);             \
        int _syc = min(max(_sy, 0), H - 1), _sxc = min(max(_sx, 0), W - 1);     \
        const float4* _ap = (const float4*)(xb + (size_t)(_syc * W + _sxc) * CIN + _ic0 + ih * 8); \
        ((float4*)areg)[0] = __ldg(_ap);                                        \
        ((float4*)areg)[1] = __ldg(_ap + 1);                                    \
        if (!_ok) {                                                             \
            _Pragma("unroll")                                                   \
            for (int c = 0; c < 8; c++) areg[c] = 0.f;                          \
        }                                                                       \
        const float4* _wp = (const float4*)(wbase + ((size_t)_tap * OCH + ocB) * CIN + _ic0 + ih * 8); \
        ((float4*)breg)[0] = __ldg(_wp);                                        \
        ((float4*)breg)[1] = __ldg(_wp + 1);                                    \
    } while (0)

    LOAD_CHUNK(0);

    for (int j = 0; j < NCHUNK; j++) {
        const int buf = j & 1;
        float* sA = smem + buf * 4096;
        float* sB = smem + 8192 + buf * 4096;

        // ---- STS: regs -> fragment-order SMEM (float2, swizzled) ----
        #pragma unroll
        for (int tig = 0; tig < 4; tig++) {
            int F = (mtw * 4 + ih) * 32 + gA * 4 + tig;
            float2 av2;
            av2.x = areg[tig];
            av2.y = areg[tig + 4];
            *(float2*)(sA + swzA(F) * 4 + rhalf * 2) = av2;
            int G = (ntw * 4 + ih) * 32 + gB * 4 + tig;
            float2 bv2;
            bv2.x = breg[tig];
            bv2.y = breg[tig + 4];
            *(float2*)(sB + swzB(G) * 2) = bv2;
        }
        __syncthreads();

        if (j + 1 < NCHUNK) LOAD_CHUNK(j + 1);   // prefetch overlaps MMA below

        // ---- MMA phase: 32 mma per warp per chunk ----
        #pragma unroll
        for (int ks = 0; ks < 4; ks++) {
            uint32_t bf[4][2];
            #pragma unroll
            for (int nf = 0; nf < 4; nf++) {
                int G = ((ntb + nf) * 4 + ks) * 32 + lane;
                float2 v = *(const float2*)(sB + swzB(G) * 2);
                bf[nf][0] = __float_as_uint(v.x);
                bf[nf][1] = __float_as_uint(v.y);
            }
            #pragma unroll
            for (int mf = 0; mf < 2; mf++) {
                int F = ((mtb + mf) * 4 + ks) * 32 + lane;
                float4 a4 = *(const float4*)(sA + swzA(F) * 4);
                // layout [a0,a2,a1,a3] -> mma order (a0,a1,a2,a3)
                uint32_t av[4] = {__float_as_uint(a4.x), __float_as_uint(a4.z),
                                  __float_as_uint(a4.y), __float_as_uint(a4.w)};
                #pragma unroll
                for (int nf = 0; nf < 4; nf++)
                    mma_tf32(acc[mf][nf], av, bf[nf]);
            }
        }
    }

    // ---- epilogue: regs -> GMEM (out[b][oc][pixel]) ----
    {
        const int g = lane >> 2, tg = lane & 3;
        #pragma unroll
        for (int mf = 0; mf < 2; mf++) {
            int pix = n0 + (mtb + mf) * 16 + g;
            #pragma unroll
            for (int nf = 0; nf < 4; nf++) {
                int oc = warpN * 32 + nf * 8 + tg * 2;
                float* o0 = out + (size_t)(b * OCH + oc) * HW;
                o0[pix]          = acc[mf][nf][0];
                o0[HW + pix]     = acc[mf][nf][1];
                o0[pix + 8]      = acc[mf][nf][2];
                o0[HW + pix + 8] = acc[mf][nf][3];
            }
        }
    }
}

#define CONV_SMEM_BYTES (4 * 4096 * 4)   // 64 KB

// ---------------------------------------------------------------------------
extern "C" void kernel_launch(void* const* d_in, const int* in_sizes, int n_in,
                              void* d_out, int out_size) {
    const float* x      = (const float*)d_in[0];   // [64,128,80,80]
    const float* weight = (const float*)d_in[1];   // [128,128,3,3]
    const float* w_att  = (const float*)d_in[2];   // [16384,1,3,3]
    const float* b_att  = (const float*)d_in[3];   // [16384]
    float* out = (float*)d_out;                    // [64,128,80,80]

    cudaFuncSetAttribute(conv_kernel, cudaFuncAttributeMaxDynamicSharedMemorySize,
                         CONV_SMEM_BYTES);

    float* xt_dev = nullptr;
    cudaGetSymbolAddress((void**)&xt_dev, g_xt);

    {
        dim3 grid(HW / 256, BATCH);     // (25, 64)
        transform_kernel<<<grid, 256>>>(x);
    }
    {
        int ntot = BATCH * CIN * 25;
        avgpool_kernel<<<(ntot + 255) / 256, 256>>>(x);
    }
    {
        int ntot = BATCH * OCH * CIN;
        att_kernel<<<(ntot + 255) / 256, 256>>>(weight, w_att, b_att);
    }
    {
        dim3 grid(HW / MTILE, BATCH);   // (50, 64)
        conv_kernel<<<grid, NTHREADS, CONV_SMEM_BYTES>>>(xt_dev, out);
    }
}

// round 14
// speedup vs baseline: 1.5632x; 1.5632x over previous
#include <cuda_runtime.h>
#include <cstdint>
#include <math.h>

#define BATCH 64
#define CIN   128
#define OCH   128
#define H     80
#define W     80
#define HW    6400
#define MTILE 128            // pixels per CTA
#define NCHUNK 36            // 9 taps * 4 ic-chunks of 32
#define NTHREADS 512

// Scratch (allocation-free rule: __device__ globals)
__device__ float g_avg[BATCH * CIN * 25];                 // [b][c][5][5]
__device__ float g_dynw[(size_t)BATCH * 9 * OCH * CIN];   // [b][tap][oc][ic], tf32-rounded
__device__ float g_xt[(size_t)BATCH * HW * CIN];          // NHWC tf32-rounded copy of x

__device__ __forceinline__ uint32_t tf32r(float v) {
    uint32_t u;
    asm("cvt.rna.tf32.f32 %0, %1;" : "=r"(u) : "f"(v));
    return u;
}

__device__ __forceinline__ void mma_tf32(float* d, const uint32_t* a, const uint32_t* bq) {
    asm volatile(
        "mma.sync.aligned.m16n8k8.row.col.f32.tf32.tf32.f32 "
        "{%0,%1,%2,%3}, {%4,%5,%6,%7}, {%8,%9}, {%0,%1,%2,%3};"
        : "+f"(d[0]), "+f"(d[1]), "+f"(d[2]), "+f"(d[3])
        : "r"(a[0]), "r"(a[1]), "r"(a[2]), "r"(a[3]), "r"(bq[0]), "r"(bq[1]));
}

// fragment-index swizzles (bijective triangular XOR; identical on store & load)
// Folds in bits 2-4 (gA/gB) AND bits 5-6 (ks) so both the ks-major store
// pattern and the lane-major load pattern are bank-conflict-free.
__device__ __forceinline__ int swzA2(int F) {
    return F ^ ((F >> 2) & 7) ^ (((F >> 5) & 3) << 2);
}
__device__ __forceinline__ int swzB2(int G) {
    return G ^ ((G >> 2) & 7) ^ (((G >> 5) & 3) << 2);
}

// ---------------------------------------------------------------------------
// Kernel T: NCHW -> NHWC transpose with tf32 pre-rounding
// ---------------------------------------------------------------------------
__global__ void __launch_bounds__(256)
transform_kernel(const float* __restrict__ x) {
    __shared__ float t[32][257];
    const int tid = threadIdx.x;
    const int b   = blockIdx.y;
    const int px0 = blockIdx.x * 256;
    const float* xb  = x    + (size_t)b * CIN * HW;
    float*       xtb = g_xt + (size_t)b * HW * CIN;

    for (int pass = 0; pass < 4; pass++) {
        const int ic0 = pass * 32;
        if (pass) __syncthreads();
        #pragma unroll 4
        for (int r = 0; r < 32; r++)
            t[r][tid] = xb[(size_t)(ic0 + r) * HW + px0 + tid];
        __syncthreads();
        float* dst = xtb + (size_t)(px0 + tid) * CIN + ic0;
        #pragma unroll
        for (int q = 0; q < 8; q++) {
            float4 v;
            v.x = __uint_as_float(tf32r(t[4 * q + 0][tid]));
            v.y = __uint_as_float(tf32r(t[4 * q + 1][tid]));
            v.z = __uint_as_float(tf32r(t[4 * q + 2][tid]));
            v.w = __uint_as_float(tf32r(t[4 * q + 3][tid]));
            ((float4*)dst)[q] = v;
        }
    }
}

// ---------------------------------------------------------------------------
// Kernel A: adaptive average pool 80x80 -> 5x5 (16x16 equal tiles)
// ---------------------------------------------------------------------------
__global__ void avgpool_kernel(const float* __restrict__ x) {
    int idx = blockIdx.x * blockDim.x + threadIdx.x;
    if (idx >= BATCH * CIN * 25) return;
    int cell = idx % 25;
    int bc   = idx / 25;
    int oy = cell / 5, ox = cell % 5;
    const float* p = x + ((size_t)bc * H + oy * 16) * W + ox * 16;
    float s = 0.f;
    #pragma unroll
    for (int r = 0; r < 16; r++) {
        const float4* q = (const float4*)(p + r * W);
        #pragma unroll
        for (int j = 0; j < 4; j++) {
            float4 v = q[j];
            s += v.x + v.y + v.z + v.w;
        }
    }
    g_avg[idx] = s * (1.f / 256.f);
}

// ---------------------------------------------------------------------------
// Kernel B: attention conv (3x3 VALID on 5x5) + sigmoid + weight modulation
// Writes tf32-pre-rounded dynamic weights in layout [b][tap][oc][ic]
// ---------------------------------------------------------------------------
__global__ void att_kernel(const float* __restrict__ weight,
                           const float* __restrict__ w_att,
                           const float* __restrict__ b_att) {
    int idx = blockIdx.x * blockDim.x + threadIdx.x;   // (b*OCH + oc)*CIN + ic
    if (idx >= BATCH * OCH * CIN) return;
    int ic  = idx % CIN;
    int boc = idx / CIN;            // b*OCH + oc
    int oc  = boc % OCH;
    int b   = boc / OCH;
    int o   = oc * CIN + ic;        // attention output channel

    float a[25];
    #pragma unroll
    for (int i = 0; i < 25; i++) a[i] = g_avg[boc * 25 + i];
    float wa[9];
    #pragma unroll
    for (int i = 0; i < 9; i++) wa[i] = w_att[o * 9 + i];
    float bias = b_att[o];

    #pragma unroll
    for (int kh = 0; kh < 3; kh++) {
        #pragma unroll
        for (int kw = 0; kw < 3; kw++) {
            float s = bias;
            #pragma unroll
            for (int i = 0; i < 3; i++)
                #pragma unroll
                for (int j = 0; j < 3; j++)
                    s += a[(kh + i) * 5 + (kw + j)] * wa[i * 3 + j];
            float sig = 1.f / (1.f + expf(-s));
            int tap = kh * 3 + kw;
            float v = weight[(oc * CIN + ic) * 9 + tap] * sig;
            g_dynw[(((size_t)b * 9 + tap) * OCH + oc) * CIN + ic] = __uint_as_float(tf32r(v));
        }
    }
}

// ---------------------------------------------------------------------------
// Kernel C: tf32 mma.sync implicit-GEMM conv — 512 threads / 16 warps
// CTA: 128 pixels (M) x 128 oc (N); K = 9 taps x 128 ic in chunks of 32.
// COALESCED loader: thread t -> px/oc = t>>2, ic-quarter = t&3; a warp's
// LDG.128 covers 8 rows' contiguous 128B ic-blocks (8 lines/instr, not 32).
// Stage regs -> fragment-order SMEM with ks-aware XOR swizzle (conflict-free).
// Double-buffered, 1 __syncthreads/chunk. Warp grid 4(M) x 4(N), tile 32x32.
// ---------------------------------------------------------------------------
__global__ void __launch_bounds__(NTHREADS)
conv_kernel(const float* __restrict__ xt, float* __restrict__ out) {
    extern __shared__ float smem[];   // [A0 4096][A1 4096][B0 4096][B1 4096] floats

    const int tid  = threadIdx.x;
    const int lane = tid & 31, wid = tid >> 5;
    const int b    = blockIdx.y;
    const int n0   = blockIdx.x * MTILE;

    // writer identities: row = tid>>2 (pixel for A, oc for B), quarter = tid&3
    const int row  = tid >> 2;           // 0..127
    const int ihq  = tid & 3;            // kstep 0..3 (8 ic each)
    const int yA   = (n0 + row) / W, xxA = (n0 + row) % W;
    const int mtw  = row >> 4;           // A mtile
    const int gA   = row & 7;
    const int rhalf = (row >> 3) & 1;
    const int ntw  = row >> 3;           // B ntile index base (row = oc)
    const int gB   = row & 7;

    const float* xb    = xt + (size_t)b * HW * CIN;
    const float* wbase = g_dynw + (size_t)b * 9 * OCH * CIN;

    // mma identities: 4x4 warp grid, warp tile 32(M) x 32(N)
    const int warpM = wid & 3, warpN = wid >> 2;
    const int mtb = warpM * 2, ntb = warpN * 4;

    float acc[2][4][4];
    #pragma unroll
    for (int mf = 0; mf < 2; mf++)
        #pragma unroll
        for (int nf = 0; nf < 4; nf++)
            #pragma unroll
            for (int q = 0; q < 4; q++) acc[mf][nf][q] = 0.f;

    float areg[8];
    float breg[8];

    // ---- chunk loader (global -> regs); coalesced: 8 rows x 128B per warp ----
    #define LOAD_CHUNK(J) do {                                                  \
        int _tap = (J) >> 2, _ic0 = ((J) & 3) * 32;                             \
        int _dy = _tap / 3 - 1, _dx = _tap % 3 - 1;                             \
        int _sy = yA + _dy, _sx = xxA + _dx;                                    \
        bool _ok = (_sy >= 0) & (_sy < H) & (_sx >= 0) & (_sx < W);             \
        int _syc = min(max(_sy, 0), H - 1), _sxc = min(max(_sx, 0), W - 1);     \
        const float4* _ap = (const float4*)(xb + (size_t)(_syc * W + _sxc) * CIN + _ic0 + ihq * 8); \
        ((float4*)areg)[0] = __ldg(_ap);                                        \
        ((float4*)areg)[1] = __ldg(_ap + 1);                                    \
        if (!_ok) {                                                             \
            _Pragma("unroll")                                                   \
            for (int c = 0; c < 8; c++) areg[c] = 0.f;                          \
        }                                                                       \
        const float4* _wp = (const float4*)(wbase + ((size_t)_tap * OCH + row) * CIN + _ic0 + ihq * 8); \
        ((float4*)breg)[0] = __ldg(_wp);                                        \
        ((float4*)breg)[1] = __ldg(_wp + 1);                                    \
    } while (0)

    LOAD_CHUNK(0);

    for (int j = 0; j < NCHUNK; j++) {
        const int buf = j & 1;
        float* sA = smem + buf * 4096;
        float* sB = smem + 8192 + buf * 4096;

        // ---- STS: regs -> fragment-order SMEM (float2, ks-aware swizzle) ----
        #pragma unroll
        for (int tig = 0; tig < 4; tig++) {
            int F = (mtw * 4 + ihq) * 32 + gA * 4 + tig;
            float2 av2;
            av2.x = areg[tig];
            av2.y = areg[tig + 4];
            *(float2*)(sA + swzA2(F) * 4 + rhalf * 2) = av2;
            int G = (ntw * 4 + ihq) * 32 + gB * 4 + tig;
            float2 bv2;
            bv2.x = breg[tig];
            bv2.y = breg[tig + 4];
            *(float2*)(sB + swzB2(G) * 2) = bv2;
        }
        __syncthreads();

        if (j + 1 < NCHUNK) LOAD_CHUNK(j + 1);   // prefetch overlaps MMA below

        // ---- MMA phase: 32 mma per warp per chunk ----
        #pragma unroll
        for (int ks = 0; ks < 4; ks++) {
            uint32_t bf[4][2];
            #pragma unroll
            for (int nf = 0; nf < 4; nf++) {
                int G = ((ntb + nf) * 4 + ks) * 32 + lane;
                float2 v = *(const float2*)(sB + swzB2(G) * 2);
                bf[nf][0] = __float_as_uint(v.x);
                bf[nf][1] = __float_as_uint(v.y);
            }
            #pragma unroll
            for (int mf = 0; mf < 2; mf++) {
                int F = ((mtb + mf) * 4 + ks) * 32 + lane;
                float4 a4 = *(const float4*)(sA + swzA2(F) * 4);
                // slot layout [rh0ch0, rh0ch1, rh1ch0, rh1ch1] -> (a0,a1,a2,a3)
                uint32_t av[4] = {__float_as_uint(a4.x), __float_as_uint(a4.z),
                                  __float_as_uint(a4.y), __float_as_uint(a4.w)};
                #pragma unroll
                for (int nf = 0; nf < 4; nf++)
                    mma_tf32(acc[mf][nf], av, bf[nf]);
            }
        }
    }

    // ---- epilogue: regs -> GMEM (out[b][oc][pixel]) ----
    {
        const int g = lane >> 2, tg = lane & 3;
        #pragma unroll
        for (int mf = 0; mf < 2; mf++) {
            int pix = n0 + (mtb + mf) * 16 + g;
            #pragma unroll
            for (int nf = 0; nf < 4; nf++) {
                int oc = warpN * 32 + nf * 8 + tg * 2;
                float* o0 = out + (size_t)(b * OCH + oc) * HW;
                o0[pix]          = acc[mf][nf][0];
                o0[HW + pix]     = acc[mf][nf][1];
                o0[pix + 8]      = acc[mf][nf][2];
                o0[HW + pix + 8] = acc[mf][nf][3];
            }
        }
    }
}

#define CONV_SMEM_BYTES (4 * 4096 * 4)   // 64 KB

// ---------------------------------------------------------------------------
extern "C" void kernel_launch(void* const* d_in, const int* in_sizes, int n_in,
                              void* d_out, int out_size) {
    const float* x      = (const float*)d_in[0];   // [64,128,80,80]
    const float* weight = (const float*)d_in[1];   // [128,128,3,3]
    const float* w_att  = (const float*)d_in[2];   // [16384,1,3,3]
    const float* b_att  = (const float*)d_in[3];   // [16384]
    float* out = (float*)d_out;                    // [64,128,80,80]

    cudaFuncSetAttribute(conv_kernel, cudaFuncAttributeMaxDynamicSharedMemorySize,
                         CONV_SMEM_BYTES);

    float* xt_dev = nullptr;
    cudaGetSymbolAddress((void**)&xt_dev, g_xt);

    {
        dim3 grid(HW / 256, BATCH);     // (25, 64)
        transform_kernel<<<grid, 256>>>(x);
    }
    {
        int ntot = BATCH * CIN * 25;
        avgpool_kernel<<<(ntot + 255) / 256, 256>>>(x);
    }
    {
        int ntot = BATCH * OCH * CIN;
        att_kernel<<<(ntot + 255) / 256, 256>>>(weight, w_att, b_att);
    }
    {
        dim3 grid(HW / MTILE, BATCH);   // (50, 64)
        conv_kernel<<<grid, NTHREADS, CONV_SMEM_BYTES>>>(xt_dev, out);
    }
}

// round 15
// speedup vs baseline: 1.9325x; 1.2362x over previous
#include <cuda_runtime.h>
#include <cstdint>
#include <math.h>

#define BATCH 64
#define CIN   128
#define OCH   128
#define H     80
#define W     80
#define HW    6400
#define MTILE 128            // pixels per CTA
#define NCHUNK 36            // 9 taps * 4 ic-chunks of 32
#define NTHREADS 512

// Scratch (allocation-free rule: __device__ globals)
__device__ float g_avg[BATCH * CIN * 25];                 // [b][c][5][5]
__device__ float g_dynw[(size_t)BATCH * 9 * OCH * CIN];   // [b][tap][oc][ic], tf32-rounded
__device__ float g_xt[(size_t)BATCH * HW * CIN];          // NHWC tf32-rounded copy of x

__device__ __forceinline__ uint32_t tf32r(float v) {
    uint32_t u;
    asm("cvt.rna.tf32.f32 %0, %1;" : "=r"(u) : "f"(v));
    return u;
}
__device__ __forceinline__ uint32_t smem_u32(const void* p) {
    uint32_t a;
    asm("{ .reg .u64 t; cvta.to.shared.u64 t, %1; cvt.u32.u64 %0, t; }" : "=r"(a) : "l"(p));
    return a;
}

__device__ __forceinline__ void mma_tf32(float* d, const uint32_t* a, const uint32_t* bq) {
    asm volatile(
        "mma.sync.aligned.m16n8k8.row.col.f32.tf32.tf32.f32 "
        "{%0,%1,%2,%3}, {%4,%5,%6,%7}, {%8,%9}, {%0,%1,%2,%3};"
        : "+f"(d[0]), "+f"(d[1]), "+f"(d[2]), "+f"(d[3])
        : "r"(a[0]), "r"(a[1]), "r"(a[2]), "r"(a[3]), "r"(bq[0]), "r"(bq[1]));
}

// ---------------------------------------------------------------------------
// Kernel T: NCHW -> NHWC transpose with tf32 pre-rounding
// ---------------------------------------------------------------------------
__global__ void __launch_bounds__(256)
transform_kernel(const float* __restrict__ x) {
    __shared__ float t[32][257];
    const int tid = threadIdx.x;
    const int b   = blockIdx.y;
    const int px0 = blockIdx.x * 256;
    const float* xb  = x    + (size_t)b * CIN * HW;
    float*       xtb = g_xt + (size_t)b * HW * CIN;

    for (int pass = 0; pass < 4; pass++) {
        const int ic0 = pass * 32;
        if (pass) __syncthreads();
        #pragma unroll 4
        for (int r = 0; r < 32; r++)
            t[r][tid] = xb[(size_t)(ic0 + r) * HW + px0 + tid];
        __syncthreads();
        float* dst = xtb + (size_t)(px0 + tid) * CIN + ic0;
        #pragma unroll
        for (int q = 0; q < 8; q++) {
            float4 v;
            v.x = __uint_as_float(tf32r(t[4 * q + 0][tid]));
            v.y = __uint_as_float(tf32r(t[4 * q + 1][tid]));
            v.z = __uint_as_float(tf32r(t[4 * q + 2][tid]));
            v.w = __uint_as_float(tf32r(t[4 * q + 3][tid]));
            ((float4*)dst)[q] = v;
        }
    }
}

// ---------------------------------------------------------------------------
// Kernel A: adaptive average pool 80x80 -> 5x5 (16x16 equal tiles)
// ---------------------------------------------------------------------------
__global__ void avgpool_kernel(const float* __restrict__ x) {
    int idx = blockIdx.x * blockDim.x + threadIdx.x;
    if (idx >= BATCH * CIN * 25) return;
    int cell = idx % 25;
    int bc   = idx / 25;
    int oy = cell / 5, ox = cell % 5;
    const float* p = x + ((size_t)bc * H + oy * 16) * W + ox * 16;
    float s = 0.f;
    #pragma unroll
    for (int r = 0; r < 16; r++) {
        const float4* q = (const float4*)(p + r * W);
        #pragma unroll
        for (int j = 0; j < 4; j++) {
            float4 v = q[j];
            s += v.x + v.y + v.z + v.w;
        }
    }
    g_avg[idx] = s * (1.f / 256.f);
}

// ---------------------------------------------------------------------------
// Kernel B: attention conv (3x3 VALID on 5x5) + sigmoid + weight modulation
// Writes tf32-pre-rounded dynamic weights in layout [b][tap][oc][ic]
// ---------------------------------------------------------------------------
__global__ void att_kernel(const float* __restrict__ weight,
                           const float* __restrict__ w_att,
                           const float* __restrict__ b_att) {
    int idx = blockIdx.x * blockDim.x + threadIdx.x;   // (b*OCH + oc)*CIN + ic
    if (idx >= BATCH * OCH * CIN) return;
    int ic  = idx % CIN;
    int boc = idx / CIN;            // b*OCH + oc
    int oc  = boc % OCH;
    int b   = boc / OCH;
    int o   = oc * CIN + ic;        // attention output channel

    float a[25];
    #pragma unroll
    for (int i = 0; i < 25; i++) a[i] = g_avg[boc * 25 + i];
    float wa[9];
    #pragma unroll
    for (int i = 0; i < 9; i++) wa[i] = w_att[o * 9 + i];
    float bias = b_att[o];

    #pragma unroll
    for (int kh = 0; kh < 3; kh++) {
        #pragma unroll
        for (int kw = 0; kw < 3; kw++) {
            float s = bias;
            #pragma unroll
            for (int i = 0; i < 3; i++)
                #pragma unroll
                for (int j = 0; j < 3; j++)
                    s += a[(kh + i) * 5 + (kw + j)] * wa[i * 3 + j];
            float sig = 1.f / (1.f + expf(-s));
            int tap = kh * 3 + kw;
            float v = weight[(oc * CIN + ic) * 9 + tap] * sig;
            g_dynw[(((size_t)b * 9 + tap) * OCH + oc) * CIN + ic] = __uint_as_float(tf32r(v));
        }
    }
}

// ---------------------------------------------------------------------------
// Kernel C: tf32 mma.sync implicit-GEMM conv — 512 threads / 16 warps
// CTA: 128 pixels (M) x 128 oc (N); K = 9 taps x 128 ic in chunks of 32.
// Producer: pure 16B-block copy via cp.async.cg (zfill for halo) into
// ROW-MAJOR smem [row][32ic] (128B rows) with per-row block swizzle
// (blk ^= row&7). Consumer: LDS.32 fragment gather — provably conflict-free
// (bank = (2ks^(lane>>2))*4 + (lane&3): all 32 banks distinct per instr).
// Double-buffered, 1 __syncthreads/chunk. Warp grid 4(M) x 4(N), tile 32x32.
// ---------------------------------------------------------------------------
__global__ void __launch_bounds__(NTHREADS)
conv_kernel(const float* __restrict__ xt, float* __restrict__ out) {
    extern __shared__ float smem[];   // bytes: [A0 16K][A1 16K][B0 16K][B1 16K]

    const int tid  = threadIdx.x;
    const int lane = tid & 31, wid = tid >> 5;
    const int b    = blockIdx.y;
    const int n0   = blockIdx.x * MTILE;

    // producer identities: row = tid>>2 (pixel for A, oc for B), 2 blocks qq,qq+1
    const int row  = tid >> 2;           // 0..127
    const int qq   = (tid & 3) * 2;      // 16B block pair within 128B row
    const int r7   = row & 7;
    const int yA   = (n0 + row) / W, xxA = (n0 + row) % W;

    const float* xb    = xt + (size_t)b * HW * CIN;
    const float* wbase = g_dynw + (size_t)b * 9 * OCH * CIN;

    const uint32_t sb = smem_u32(smem);
    const uint32_t aD0 = sb + row * 128 + (((qq)     ^ r7) << 4);
    const uint32_t aD1 = sb + row * 128 + (((qq + 1) ^ r7) << 4);
    const uint32_t bD0 = aD0 + 32768u;
    const uint32_t bD1 = aD1 + 32768u;

    // mma identities: 4x4 warp grid, warp tile 32(M) x 32(N)
    const int warpM = wid & 3, warpN = wid >> 2;
    const int mtb = warpM * 2, ntb = warpN * 4;
    const int lg = lane >> 2, tg = lane & 3;

    float acc[2][4][4];
    #pragma unroll
    for (int mf = 0; mf < 2; mf++)
        #pragma unroll
        for (int nf = 0; nf < 4; nf++)
            #pragma unroll
            for (int q = 0; q < 4; q++) acc[mf][nf][q] = 0.f;

    // per-ks swizzled fragment byte offsets (lane constants)
    uint32_t off0[4], off1[4];
    #pragma unroll
    for (int ks = 0; ks < 4; ks++) {
        off0[ks] = (uint32_t)((((2 * ks)     ^ lg) << 4) + tg * 4);
        off1[ks] = (uint32_t)((((2 * ks + 1) ^ lg) << 4) + tg * 4);
    }

    // ---- producer: 4x cp.async.cg 16B per chunk ----
    #define FILL(J) do {                                                        \
        int _tap = (J) >> 2, _ic0 = ((J) & 3) * 32;                             \
        int _dy = _tap / 3 - 1, _dx = _tap % 3 - 1;                             \
        int _sy = yA + _dy, _sx = xxA + _dx;                                    \
        bool _ok = (_sy >= 0) & (_sy < H) & (_sx >= 0) & (_sx < W);             \
        int _syc = min(max(_sy, 0), H - 1), _sxc = min(max(_sx, 0), W - 1);     \
        const float* _ap = xb + (size_t)(_syc * W + _sxc) * CIN + _ic0 + qq * 4;\
        uint32_t _sz = _ok ? 16u : 0u;                                          \
        uint32_t _bo = ((J) & 1) * 16384u;                                      \
        asm volatile("cp.async.cg.shared.global [%0], [%1], 16, %2;"            \
                     :: "r"(aD0 + _bo), "l"(_ap), "r"(_sz) : "memory");         \
        asm volatile("cp.async.cg.shared.global [%0], [%1], 16, %2;"            \
                     :: "r"(aD1 + _bo), "l"(_ap + 4), "r"(_sz) : "memory");     \
        const float* _wp = wbase + ((size_t)_tap * OCH + row) * CIN + _ic0 + qq * 4; \
        asm volatile("cp.async.cg.shared.global [%0], [%1], 16;"                \
                     :: "r"(bD0 + _bo), "l"(_wp) : "memory");                   \
        asm volatile("cp.async.cg.shared.global [%0], [%1], 16;"                \
                     :: "r"(bD1 + _bo), "l"(_wp + 4) : "memory");               \
        asm volatile("cp.async.commit_group;" ::: "memory");                    \
    } while (0)

    FILL(0);

    for (int j = 0; j < NCHUNK; j++) {
        asm volatile("cp.async.wait_group 0;" ::: "memory");
        __syncthreads();                       // buf j fully visible

        if (j + 1 < NCHUNK) FILL(j + 1);       // overlaps MMA below

        const char* sAb = (const char*)smem + (j & 1) * 16384;
        const char* sBb = sAb + 32768;

        #pragma unroll
        for (int ks = 0; ks < 4; ks++) {
            const uint32_t o0 = off0[ks], o1 = off1[ks];
            uint32_t bf[4][2];
            #pragma unroll
            for (int nf = 0; nf < 4; nf++) {
                int rn = ((ntb + nf) * 8 + lg) * 128;
                bf[nf][0] = *(const uint32_t*)(sBb + rn + o0);
                bf[nf][1] = *(const uint32_t*)(sBb + rn + o1);
            }
            #pragma unroll
            for (int mf = 0; mf < 2; mf++) {
                int r0 = ((mtb + mf) * 16 + lg) * 128;
                int r1 = r0 + 8 * 128;
                uint32_t av[4];
                av[0] = *(const uint32_t*)(sAb + r0 + o0);
                av[1] = *(const uint32_t*)(sAb + r1 + o0);
                av[2] = *(const uint32_t*)(sAb + r0 + o1);
                av[3] = *(const uint32_t*)(sAb + r1 + o1);
                #pragma unroll
                for (int nf = 0; nf < 4; nf++)
                    mma_tf32(acc[mf][nf], av, bf[nf]);
            }
        }
    }

    // ---- epilogue: regs -> GMEM (out[b][oc][pixel]) ----
    {
        #pragma unroll
        for (int mf = 0; mf < 2; mf++) {
            int pix = n0 + (mtb + mf) * 16 + lg;
            #pragma unroll
            for (int nf = 0; nf < 4; nf++) {
                int oc = warpN * 32 + nf * 8 + tg * 2;
                float* o0p = out + (size_t)(b * OCH + oc) * HW;
                o0p[pix]          = acc[mf][nf][0];
                o0p[HW + pix]     = acc[mf][nf][1];
                o0p[pix + 8]      = acc[mf][nf][2];
                o0p[HW + pix + 8] = acc[mf][nf][3];
            }
        }
    }
}

#define CONV_SMEM_BYTES 65536   // 64 KB

// ---------------------------------------------------------------------------
extern "C" void kernel_launch(void* const* d_in, const int* in_sizes, int n_in,
                              void* d_out, int out_size) {
    const float* x      = (const float*)d_in[0];   // [64,128,80,80]
    const float* weight = (const float*)d_in[1];   // [128,128,3,3]
    const float* w_att  = (const float*)d_in[2];   // [16384,1,3,3]
    const float* b_att  = (const float*)d_in[3];   // [16384]
    float* out = (float*)d_out;                    // [64,128,80,80]

    cudaFuncSetAttribute(conv_kernel, cudaFuncAttributeMaxDynamicSharedMemorySize,
                         CONV_SMEM_BYTES);

    float* xt_dev = nullptr;
    cudaGetSymbolAddress((void**)&xt_dev, g_xt);

    {
        dim3 grid(HW / 256, BATCH);     // (25, 64)
        transform_kernel<<<grid, 256>>>(x);
    }
    {
        int ntot = BATCH * CIN * 25;
        avgpool_kernel<<<(ntot + 255) / 256, 256>>>(x);
    }
    {
        int ntot = BATCH * OCH * CIN;
        att_kernel<<<(ntot + 255) / 256, 256>>>(weight, w_att, b_att);
    }
    {
        dim3 grid(HW / MTILE, BATCH);   // (50, 64)
        conv_kernel<<<grid, NTHREADS, CONV_SMEM_BYTES>>>(xt_dev, out);
    }
}